// round 1
// baseline (speedup 1.0000x reference)
#include <cuda_runtime.h>

// ---------------- problem constants ----------------
#define Bn    32
#define Hh    56
#define Wd    56
#define Cc    128
#define NHh   4
#define HDd   32
#define Ss    7
#define POSs  2
#define KYy   7
#define KXx   35
#define NKk   245      // KY*KX
#define NQq   49       // S*S
#define NPHh  8
#define NPWw  8
#define SCALE 0.17677669529663687f   // 32^-0.5

// ---------------- smem layout (float offsets) ----------------
// q  : 49 rows x 32, stride 33 (bank-conflict pad)
// k  : 245 rows x 32, stride 33
// v  : 248 rows x 32, stride 33 (rows 245..247 zeroed for k-unroll tail)
// sim: 49 rows x 248 (cols 245..247 zeroed after softmax)
// rowsum: 49
#define OFF_Q    0
#define OFF_K    1620        // 49*33=1617 -> pad to 1620
#define OFF_V    9708        // 1620 + 8085(=245*33) -> pad to 9708
#define OFF_S    17892       // 9708 + 8184(=248*33)
#define OFF_SUM  30044       // 17892 + 12152(=49*248)
#define SMEM_FLOATS 30096
#define SMEM_BYTES (SMEM_FLOATS * 4)

__global__ __launch_bounds__(256, 1)
void lepe_attn_kernel(const float* __restrict__ qkv,
                      const float* __restrict__ w_lepe,
                      const float* __restrict__ b_lepe,
                      float* __restrict__ out)
{
    extern __shared__ float sm[];

    const int bid = blockIdx.x;
    const int h   = bid & 3;
    const int pw  = (bid >> 2) & 7;
    const int ph  = (bid >> 5) & 7;
    const int b   = bid >> 8;
    const int tid = threadIdx.x;

    const size_t plane = (size_t)Hh * Wd * Cc;          // 401408
    const float* qg = qkv + (size_t)b * plane;
    const float* kg = qkv + (size_t)Bn * plane     + (size_t)b * plane;
    const float* vg = qkv + (size_t)2 * Bn * plane + (size_t)b * plane;
    const int cbase = h * HDd;

    // -------- load q (scaled) --------
    for (int idx = tid; idx < NQq * 8; idx += 256) {
        int r  = idx >> 3;
        int dv = (idx & 7) << 2;
        int qi = r / 7, qj = r - 7 * (r / 7);
        int pix = (ph * 7 + qi) * Wd + pw * 7 + qj;
        float4 val = *(const float4*)(qg + (size_t)pix * Cc + cbase + dv);
        float* dst = sm + OFF_Q + r * 33 + dv;
        dst[0] = val.x * SCALE; dst[1] = val.y * SCALE;
        dst[2] = val.z * SCALE; dst[3] = val.w * SCALE;
    }

    // -------- load k, v (zero-padded out-of-image cols; v rows 245..247 zero) --------
    for (int idx = tid; idx < 248 * 8; idx += 256) {
        int kk = idx >> 3;
        int dv = (idx & 7) << 2;
        int ky = kk / 35, kx = kk - 35 * (kk / 35);
        int x = pw * 7 + kx - 14;
        int y = ph * 7 + ky;
        float4 kv = make_float4(0.f, 0.f, 0.f, 0.f);
        float4 vv = make_float4(0.f, 0.f, 0.f, 0.f);
        if (kk < NKk && x >= 0 && x < Wd) {
            size_t g = (size_t)(y * Wd + x) * Cc + cbase + dv;
            kv = *(const float4*)(kg + g);
            vv = *(const float4*)(vg + g);
        }
        if (kk < NKk) {
            float* kd = sm + OFF_K + kk * 33 + dv;
            kd[0] = kv.x; kd[1] = kv.y; kd[2] = kv.z; kd[3] = kv.w;
        }
        float* vd = sm + OFF_V + kk * 33 + dv;
        vd[0] = vv.x; vd[1] = vv.y; vd[2] = vv.z; vd[3] = vv.w;
    }
    __syncthreads();

    // -------- sim = (q*SCALE) @ k^T : 49 x 245, thread grid 7x35, 7x7 reg tile --------
    if (tid < 245) {
        const int tr = tid / 35;
        const int tc = tid - 35 * tr;
        float acc[7][7];
        #pragma unroll
        for (int i = 0; i < 7; i++)
            #pragma unroll
            for (int j = 0; j < 7; j++) acc[i][j] = 0.f;

        const float* qb = sm + OFF_Q + tr * 33;     // rows tr + 7i
        const float* kb = sm + OFF_K + tc * 33;     // cols tc + 35j
        #pragma unroll 8
        for (int kk = 0; kk < 32; kk++) {
            float a[7], bb[7];
            #pragma unroll
            for (int i = 0; i < 7; i++) a[i]  = qb[i * (7 * 33) + kk];
            #pragma unroll
            for (int j = 0; j < 7; j++) bb[j] = kb[j * (35 * 33) + kk];
            #pragma unroll
            for (int i = 0; i < 7; i++)
                #pragma unroll
                for (int j = 0; j < 7; j++)
                    acc[i][j] = fmaf(a[i], bb[j], acc[i][j]);
        }
        #pragma unroll
        for (int i = 0; i < 7; i++)
            #pragma unroll
            for (int j = 0; j < 7; j++)
                sm[OFF_S + (tr + 7 * i) * 248 + tc + 35 * j] = acc[i][j];
    }
    __syncthreads();

    // -------- softmax per row (warp per row), store exp in-place + rowsum --------
    {
        const int warp = tid >> 5, lane = tid & 31;
        for (int r = warp; r < NQq; r += 8) {
            float* row = sm + OFF_S + r * 248;
            float vals[8];
            float mx = -1e30f;
            #pragma unroll
            for (int u = 0; u < 8; u++) {
                int c = lane + u * 32;
                vals[u] = (c < NKk) ? row[c] : -1e30f;
                mx = fmaxf(mx, vals[u]);
            }
            #pragma unroll
            for (int s = 16; s > 0; s >>= 1)
                mx = fmaxf(mx, __shfl_xor_sync(0xffffffffu, mx, s));
            float sum = 0.f;
            #pragma unroll
            for (int u = 0; u < 8; u++) {
                int c = lane + u * 32;
                float e = (c < NKk) ? __expf(vals[u] - mx) : 0.f;
                if (c < 248) row[c] = e;   // cols 245..247 get 0
                sum += e;
            }
            #pragma unroll
            for (int s = 16; s > 0; s >>= 1)
                sum += __shfl_xor_sync(0xffffffffu, sum, s);
            if (lane == 0) sm[OFF_SUM + r] = sum;
        }
    }
    __syncthreads();

    // -------- out = attn @ v (k-unroll 4, float4 attn loads) + LePE, store --------
    if (tid < 224) {
        const int tr = tid >> 5;     // qj  (column within window)
        const int td = tid & 31;     // head-dim lane
        float acc[7];
        #pragma unroll
        for (int i = 0; i < 7; i++) acc[i] = 0.f;

        #pragma unroll 2
        for (int k4 = 0; k4 < 62; k4++) {
            const int k = k4 * 4;
            const float v0 = sm[OFF_V + (k + 0) * 33 + td];
            const float v1 = sm[OFF_V + (k + 1) * 33 + td];
            const float v2 = sm[OFF_V + (k + 2) * 33 + td];
            const float v3 = sm[OFF_V + (k + 3) * 33 + td];
            #pragma unroll
            for (int i = 0; i < 7; i++) {
                float4 a = *(const float4*)(sm + OFF_S + (tr + 7 * i) * 248 + k);
                acc[i] = fmaf(a.x, v0, acc[i]);
                acc[i] = fmaf(a.y, v1, acc[i]);
                acc[i] = fmaf(a.z, v2, acc[i]);
                acc[i] = fmaf(a.w, v3, acc[i]);
            }
        }

        // LePE weights for this channel
        const int c = cbase + td;
        const float bl = b_lepe[c];
        float wl[9];
        #pragma unroll
        for (int w9 = 0; w9 < 9; w9++) wl[w9] = w_lepe[w9 * Cc + c];

        const int qj = tr;
        #pragma unroll
        for (int i = 0; i < 7; i++) {           // qi = i, row r = i*7 + qj
            const int r = tr + 7 * i;
            float o = acc[i] / sm[OFF_SUM + r];

            // depthwise 3x3 on the 7x7 window-center V tile (zero pad at window edges)
            float l = bl;
            #pragma unroll
            for (int di = -1; di <= 1; di++) {
                const int yy = i + di;
                if (yy < 0 || yy >= 7) continue;
                #pragma unroll
                for (int dj = -1; dj <= 1; dj++) {
                    const int xx = qj + dj;
                    if (xx < 0 || xx >= 7) continue;
                    l = fmaf(wl[(di + 1) * 3 + (dj + 1)],
                             sm[OFF_V + (yy * 35 + 14 + xx) * 33 + td], l);
                }
            }
            o += l;

            const int pix = (ph * 7 + i) * Wd + pw * 7 + qj;
            out[(size_t)b * plane + (size_t)pix * Cc + c] = o;
        }
    }
}

extern "C" void kernel_launch(void* const* d_in, const int* in_sizes, int n_in,
                              void* d_out, int out_size)
{
    const float* qkv    = (const float*)d_in[0];
    const float* w_lepe = (const float*)d_in[1];
    const float* b_lepe = (const float*)d_in[2];
    float* out          = (float*)d_out;

    cudaFuncSetAttribute(lepe_attn_kernel,
                         cudaFuncAttributeMaxDynamicSharedMemorySize, SMEM_BYTES);
    lepe_attn_kernel<<<Bn * NPHh * NPWw * NHh, 256, SMEM_BYTES>>>(qkv, w_lepe, b_lepe, out);
}

// round 2
// speedup vs baseline: 1.4919x; 1.4919x over previous
#include <cuda_runtime.h>

// ---------------- problem constants ----------------
#define Bn    32
#define Hh    56
#define Wd    56
#define Cc    128
#define NHh   4
#define HDd   32
#define Ss    7
#define NKk   245      // KY*KX = 7*35
#define NQq   49       // S*S
#define SCALE 0.17677669529663687f   // 32^-0.5

// ---------------- smem layout (float offsets) ----------------
// Phase 1 (load + QK^T read):  Q at 0 (49 x 32, stride 33), K at 1620 (245 x 33)
// Phase 2 (after sync):        sim overlays Q+K region: 49 rows x 248 = 12152 floats
// V lives behind sim the whole time: 248 rows x 33 (rows 245..247 zeroed)
// rowsum: 49 floats at the end
#define OFF_Q    0
#define OFF_K    1620        // 49*33=1617 -> pad to 1620
#define OFF_S    0           // sim overlays Q+K after the GEMM's read phase
#define OFF_V    12152       // right after sim (sim needs 49*248 = 12152)
#define OFF_SUM  20336       // 12152 + 248*33(=8184)
#define SMEM_FLOATS 20400
#define SMEM_BYTES (SMEM_FLOATS * 4)   // 81,600 B -> 2 CTAs/SM

__global__ __launch_bounds__(256, 2)
void lepe_attn_kernel(const float* __restrict__ qkv,
                      const float* __restrict__ w_lepe,
                      const float* __restrict__ b_lepe,
                      float* __restrict__ out)
{
    extern __shared__ float sm[];

    const int bid = blockIdx.x;
    const int h   = bid & 3;
    const int pw  = (bid >> 2) & 7;
    const int ph  = (bid >> 5) & 7;
    const int b   = bid >> 8;
    const int tid = threadIdx.x;

    const size_t plane = (size_t)Hh * Wd * Cc;          // 401408
    const float* qg = qkv + (size_t)b * plane;
    const float* kg = qkv + (size_t)Bn * plane     + (size_t)b * plane;
    const float* vg = qkv + (size_t)2 * Bn * plane + (size_t)b * plane;
    const int cbase = h * HDd;

    // -------- load q (scaled) --------
    for (int idx = tid; idx < NQq * 8; idx += 256) {
        int r  = idx >> 3;
        int dv = (idx & 7) << 2;
        int qi = r / 7, qj = r - 7 * (r / 7);
        int pix = (ph * 7 + qi) * Wd + pw * 7 + qj;
        float4 val = *(const float4*)(qg + (size_t)pix * Cc + cbase + dv);
        float* dst = sm + OFF_Q + r * 33 + dv;
        dst[0] = val.x * SCALE; dst[1] = val.y * SCALE;
        dst[2] = val.z * SCALE; dst[3] = val.w * SCALE;
    }

    // -------- load k, v (zero-padded out-of-image cols; v rows 245..247 zero) --------
    for (int idx = tid; idx < 248 * 8; idx += 256) {
        int kk = idx >> 3;
        int dv = (idx & 7) << 2;
        int ky = kk / 35, kx = kk - 35 * (kk / 35);
        int x = pw * 7 + kx - 14;
        int y = ph * 7 + ky;
        float4 kv = make_float4(0.f, 0.f, 0.f, 0.f);
        float4 vv = make_float4(0.f, 0.f, 0.f, 0.f);
        if (kk < NKk && x >= 0 && x < Wd) {
            size_t g = (size_t)(y * Wd + x) * Cc + cbase + dv;
            kv = *(const float4*)(kg + g);
            vv = *(const float4*)(vg + g);
        }
        if (kk < NKk) {
            float* kd = sm + OFF_K + kk * 33 + dv;
            kd[0] = kv.x; kd[1] = kv.y; kd[2] = kv.z; kd[3] = kv.w;
        }
        float* vd = sm + OFF_V + kk * 33 + dv;
        vd[0] = vv.x; vd[1] = vv.y; vd[2] = vv.z; vd[3] = vv.w;
    }
    __syncthreads();

    // -------- sim = (q*SCALE) @ k^T : 49 x 245, thread grid 7x35, 7x7 reg tile ----
    // acc stays in registers across the barrier; sim is then written OVER Q+K.
    {
        float acc[7][7];
        int tr = 0, tc = 0;
        if (tid < 245) {
            tr = tid / 35;
            tc = tid - 35 * tr;
            #pragma unroll
            for (int i = 0; i < 7; i++)
                #pragma unroll
                for (int j = 0; j < 7; j++) acc[i][j] = 0.f;

            const float* qb = sm + OFF_Q + tr * 33;     // rows tr + 7i
            const float* kb = sm + OFF_K + tc * 33;     // cols tc + 35j
            #pragma unroll 8
            for (int kk = 0; kk < 32; kk++) {
                float a[7], bb[7];
                #pragma unroll
                for (int i = 0; i < 7; i++) a[i]  = qb[i * (7 * 33) + kk];
                #pragma unroll
                for (int j = 0; j < 7; j++) bb[j] = kb[j * (35 * 33) + kk];
                #pragma unroll
                for (int i = 0; i < 7; i++)
                    #pragma unroll
                    for (int j = 0; j < 7; j++)
                        acc[i][j] = fmaf(a[i], bb[j], acc[i][j]);
            }
        }
        __syncthreads();   // everyone done READING Q,K -> safe to overwrite with sim
        if (tid < 245) {
            #pragma unroll
            for (int i = 0; i < 7; i++)
                #pragma unroll
                for (int j = 0; j < 7; j++)
                    sm[OFF_S + (tr + 7 * i) * 248 + tc + 35 * j] = acc[i][j];
        }
    }
    __syncthreads();

    // -------- softmax per row (warp per row), store exp in-place + rowsum --------
    {
        const int warp = tid >> 5, lane = tid & 31;
        for (int r = warp; r < NQq; r += 8) {
            float* row = sm + OFF_S + r * 248;
            float vals[8];
            float mx = -1e30f;
            #pragma unroll
            for (int u = 0; u < 8; u++) {
                int c = lane + u * 32;
                vals[u] = (c < NKk) ? row[c] : -1e30f;
                mx = fmaxf(mx, vals[u]);
            }
            #pragma unroll
            for (int s = 16; s > 0; s >>= 1)
                mx = fmaxf(mx, __shfl_xor_sync(0xffffffffu, mx, s));
            float sum = 0.f;
            #pragma unroll
            for (int u = 0; u < 8; u++) {
                int c = lane + u * 32;
                float e = (c < NKk) ? __expf(vals[u] - mx) : 0.f;
                if (c < 248) row[c] = e;   // cols 245..247 get 0
                sum += e;
            }
            #pragma unroll
            for (int s = 16; s > 0; s >>= 1)
                sum += __shfl_xor_sync(0xffffffffu, sum, s);
            if (lane == 0) sm[OFF_SUM + r] = sum;
        }
    }
    __syncthreads();

    // -------- out = attn @ v (k-unroll 4, float4 broadcast attn loads) + LePE ----
    if (tid < 224) {
        const int tr = tid >> 5;     // qj  (column within window)
        const int td = tid & 31;     // head-dim lane
        float acc[7];
        #pragma unroll
        for (int i = 0; i < 7; i++) acc[i] = 0.f;

        #pragma unroll 2
        for (int k4 = 0; k4 < 62; k4++) {
            const int k = k4 * 4;
            const float v0 = sm[OFF_V + (k + 0) * 33 + td];
            const float v1 = sm[OFF_V + (k + 1) * 33 + td];
            const float v2 = sm[OFF_V + (k + 2) * 33 + td];
            const float v3 = sm[OFF_V + (k + 3) * 33 + td];
            #pragma unroll
            for (int i = 0; i < 7; i++) {
                float4 a = *(const float4*)(sm + OFF_S + (tr + 7 * i) * 248 + k);
                acc[i] = fmaf(a.x, v0, acc[i]);
                acc[i] = fmaf(a.y, v1, acc[i]);
                acc[i] = fmaf(a.z, v2, acc[i]);
                acc[i] = fmaf(a.w, v3, acc[i]);
            }
        }

        // LePE weights for this channel
        const int c = cbase + td;
        const float bl = b_lepe[c];
        float wl[9];
        #pragma unroll
        for (int w9 = 0; w9 < 9; w9++) wl[w9] = w_lepe[w9 * Cc + c];

        const int qj = tr;
        #pragma unroll
        for (int i = 0; i < 7; i++) {           // qi = i, row r = i*7 + qj
            const int r = tr + 7 * i;
            float o = acc[i] / sm[OFF_SUM + r];

            // depthwise 3x3 on the 7x7 window-center V tile (zero pad at window edges)
            float l = bl;
            #pragma unroll
            for (int di = -1; di <= 1; di++) {
                const int yy = i + di;
                if (yy < 0 || yy >= 7) continue;
                #pragma unroll
                for (int dj = -1; dj <= 1; dj++) {
                    const int xx = qj + dj;
                    if (xx < 0 || xx >= 7) continue;
                    l = fmaf(wl[(di + 1) * 3 + (dj + 1)],
                             sm[OFF_V + (yy * 35 + 14 + xx) * 33 + td], l);
                }
            }
            o += l;

            const int pix = (ph * 7 + i) * Wd + pw * 7 + qj;
            out[(size_t)b * plane + (size_t)pix * Cc + c] = o;
        }
    }
}

extern "C" void kernel_launch(void* const* d_in, const int* in_sizes, int n_in,
                              void* d_out, int out_size)
{
    const float* qkv    = (const float*)d_in[0];
    const float* w_lepe = (const float*)d_in[1];
    const float* b_lepe = (const float*)d_in[2];
    float* out          = (float*)d_out;

    cudaFuncSetAttribute(lepe_attn_kernel,
                         cudaFuncAttributeMaxDynamicSharedMemorySize, SMEM_BYTES);
    lepe_attn_kernel<<<Bn * 8 * 8 * NHh, 256, SMEM_BYTES>>>(qkv, w_lepe, b_lepe, out);
}